// round 15
// baseline (speedup 1.0000x reference)
#include <cuda_runtime.h>
#include <cuda_fp16.h>
#include <math.h>
#include <stdint.h>

#define NMAX 100000
#define KNBR 16

// Scratch (static __device__ — allocation-guard safe)
__device__ __half g_hA[NMAX * 384];
__device__ __half g_hB[NMAX * 256];
__device__ float  g_bufC[NMAX * 512];
__device__ __half g_hF[NMAX * 128];     // half features
__device__ __half g_hW[720896];         // half transposed weights (incl. [512][640] concat)
__device__ __half g_hD[NMAX * 256];     // m3 hidden (side stream)

__device__ __forceinline__ float to_tf32(float x) {
    float y;
    asm("cvt.rna.tf32.f32 %0, %1;" : "=f"(y) : "f"(x));
    return y;
}

__device__ __forceinline__ uint32_t smem_u32(const void* p) {
    uint32_t a;
    asm("{ .reg .u64 t; cvta.to.shared.u64 t, %1; cvt.u32.u64 %0, t; }"
        : "=r"(a) : "l"(p));
    return a;
}

__device__ __forceinline__ void cp_async16(uint32_t dst, const void* src, int szb) {
    asm volatile("cp.async.cg.shared.global [%0], [%1], 16, %2;"
                 :: "r"(dst), "l"(src), "r"(szb));
}

#define LDSM_X4(r0, r1, r2, r3, addr)                                         \
    asm volatile("ldmatrix.sync.aligned.m8n8.x4.shared.b16 {%0,%1,%2,%3}, [%4];" \
        : "=r"(r0), "=r"(r1), "=r"(r2), "=r"(r3) : "r"(addr))

#define MMA_F16(C, a0, a1, a2, a3, b0, b1)                                    \
    asm volatile(                                                             \
        "mma.sync.aligned.m16n8k16.row.col.f32.f16.f16.f32 "                  \
        "{%0,%1,%2,%3}, {%4,%5,%6,%7}, {%8,%9}, {%0,%1,%2,%3};"               \
        : "+f"((C)[0]), "+f"((C)[1]), "+f"((C)[2]), "+f"((C)[3])              \
        : "r"(a0), "r"(a1), "r"(a2), "r"(a3), "r"(b0), "r"(b1))

#define MMA_TF32(C, a0, a1, a2, a3, b0, b1)                                   \
    asm volatile(                                                             \
        "mma.sync.aligned.m16n8k8.row.col.f32.tf32.tf32.f32 "                 \
        "{%0,%1,%2,%3}, {%4,%5,%6,%7}, {%8,%9}, {%0,%1,%2,%3};"               \
        : "+f"((C)[0]), "+f"((C)[1]), "+f"((C)[2]), "+f"((C)[3])              \
        : "r"(a0), "r"(a1), "r"(a2), "r"(a3), "r"(b0), "r"(b1))

// ---------------------------------------------------------------------------
// Pre-round: weights -> half, transposed to [O][ld] with column offset.
// ---------------------------------------------------------------------------
struct WPackT {
    const float* s[10];
    int Kd[10];
    int Od[10];
    int ld[10];
    int coff[10];
    int off[10];
};

__global__ void round_weightsT_kernel(WPackT p, __half* dst) {
    int m = blockIdx.y;
    int i = blockIdx.x * blockDim.x + threadIdx.x;
    int Kd = p.Kd[m], Od = p.Od[m];
    if (i < Kd * Od) {
        int k = i / Od, o = i % Od;
        dst[p.off[m] + (size_t)o * p.ld[m] + p.coff[m] + k] =
            __float2half_rn(p.s[m][i]);
    }
}

__global__ void round_feat_kernel(const float* __restrict__ src,
                                  __half* __restrict__ dst, int n) {
    int i = blockIdx.x * blockDim.x + threadIdx.x;
    if (i < n) dst[i] = __float2half_rn(src[i]);
}

// ---------------------------------------------------------------------------
// Shared tiling constants
// ---------------------------------------------------------------------------
#define ASTH 40
#define AS_HL (128 * ASTH)
#define OP_B  (AS_HL * 2)
#define STG_B (2 * OP_B)
#define NSTG 4
#define HGEMM_SMEM (NSTG * STG_B)       // 81920
#define SINT 264
#define MLP2_SMEM (NSTG * STG_B + 128 * SINT * 2)   // 149504

// ---------------------------------------------------------------------------
// fp16 tensor-core GEMM (dual-A capable). Same as R13/R14.
// ---------------------------------------------------------------------------
__device__ __forceinline__ void hgemm_issue2(
    const __half* __restrict__ Abase, int strideA, int kloc,
    const __half* __restrict__ Wt, int KW, int kw,
    int M, int bm, int bn, int tid, uint32_t sbase, int stage)
{
    uint32_t so = sbase + stage * STG_B;
#pragma unroll
    for (int i = 0; i < 2; i++) {
        int id = tid + 256 * i;
        int row = id >> 2, cc = id & 3;
        const __half* src = Abase + (size_t)(bm + row) * strideA + kloc + cc * 8;
        cp_async16(so + (row * ASTH + cc * 8) * 2, src, (bm + row) < M ? 16 : 0);
    }
#pragma unroll
    for (int i = 0; i < 2; i++) {
        int id = tid + 256 * i;
        int row = id >> 2, cc = id & 3;
        const __half* src = Wt + (size_t)(bn + row) * KW + kw + cc * 8;
        cp_async16(so + OP_B + (row * ASTH + cc * 8) * 2, src, 16);
    }
    asm volatile("cp.async.commit_group;");
}

__global__ __launch_bounds__(256, 2) void hgemm_kernel(
    const __half* __restrict__ A, const __half* __restrict__ A2,
    const __half* __restrict__ Wt,
    const float* __restrict__ bias, const float* __restrict__ bias2,
    const float* __restrict__ res,
    void* __restrict__ Cout, int M, int K, int K2, int O, int act)
{
    extern __shared__ float dsm[];
    uint32_t sb = smem_u32(dsm);

    int tid = threadIdx.x, lane = tid & 31, wid = tid >> 5;
    int bm = blockIdx.x * 128, bn = blockIdx.y * 128;
    int wm = wid & 1, wn = wid >> 1;
    int gid = lane >> 2, tig = lane & 3;
    bool hout = (act & 8) != 0;
    int actv = act & 3;
    int KW = K + K2;
    int nk1 = K / 32, nk = KW / 32;

    int aRow = wm * 64 + ((lane >> 3) & 1) * 8 + (lane & 7);
    int aCol = (lane >> 4) * 8;
    int bRow = wn * 32 + ((lane >> 4) & 1) * 8 + (lane & 7);
    int bCol = ((lane >> 3) & 1) * 8;
    uint32_t aOff = (uint32_t)(aRow * ASTH + aCol) * 2;
    uint32_t bOff = OP_B + (uint32_t)(bRow * ASTH + bCol) * 2;

    float c[4][4][4];
#pragma unroll
    for (int mt = 0; mt < 4; mt++)
#pragma unroll
        for (int nt = 0; nt < 4; nt++)
#pragma unroll
            for (int q = 0; q < 4; q++) c[mt][nt][q] = 0.f;

    auto issue = [&](int kt, int stage) {
        const __half* Ab; int strA, kloc;
        if (kt < nk1) { Ab = A;  strA = K;  kloc = kt * 32; }
        else          { Ab = A2; strA = K2; kloc = (kt - nk1) * 32; }
        hgemm_issue2(Ab, strA, kloc, Wt, KW, kt * 32, M, bm, bn, tid, sb, stage);
    };

    issue(0, 0);
    issue(1, 1);

    for (int kt = 0; kt < nk; kt++) {
        int s = kt & 3;
        if (kt + 2 < nk) {
            issue(kt + 2, (kt + 2) & 3);
            asm volatile("cp.async.wait_group 2;");
        } else if (kt + 1 < nk) {
            asm volatile("cp.async.wait_group 1;");
        } else {
            asm volatile("cp.async.wait_group 0;");
        }
        __syncthreads();

        uint32_t sAddr = sb + s * STG_B;
#pragma unroll
        for (int ks = 0; ks < 2; ks++) {
            uint32_t kOff = (uint32_t)(ks * 16) * 2;
            uint32_t af[4][4];
#pragma unroll
            for (int mt = 0; mt < 4; mt++)
                LDSM_X4(af[mt][0], af[mt][1], af[mt][2], af[mt][3],
                        sAddr + aOff + (uint32_t)(mt * 16 * ASTH) * 2 + kOff);
            uint32_t bf[4][2];
#pragma unroll
            for (int nt2 = 0; nt2 < 2; nt2++)
                LDSM_X4(bf[2 * nt2][0], bf[2 * nt2][1],
                        bf[2 * nt2 + 1][0], bf[2 * nt2 + 1][1],
                        sAddr + bOff + (uint32_t)(nt2 * 16 * ASTH) * 2 + kOff);
#pragma unroll
            for (int mt = 0; mt < 4; mt++)
#pragma unroll
                for (int nt = 0; nt < 4; nt++)
                    MMA_F16(c[mt][nt], af[mt][0], af[mt][1], af[mt][2],
                            af[mt][3], bf[nt][0], bf[nt][1]);
        }
    }

#pragma unroll
    for (int mt = 0; mt < 4; mt++) {
        int r0 = bm + wm * 64 + mt * 16 + gid;
        int r1 = r0 + 8;
        bool v0 = r0 < M, v1 = r1 < M;
#pragma unroll
        for (int nt = 0; nt < 4; nt++) {
            int col = bn + wn * 32 + nt * 8 + tig * 2;
            float2 bb = *(const float2*)(bias + col);
            if (bias2) {
                float2 b2 = *(const float2*)(bias2 + col);
                bb.x += b2.x; bb.y += b2.y;
            }
            float2 o0 = make_float2(c[mt][nt][0] + bb.x, c[mt][nt][1] + bb.y);
            float2 o1 = make_float2(c[mt][nt][2] + bb.x, c[mt][nt][3] + bb.y);
            if (actv == 1) {
                o0.x = fmaxf(o0.x, 0.f); o0.y = fmaxf(o0.y, 0.f);
                o1.x = fmaxf(o1.x, 0.f); o1.y = fmaxf(o1.y, 0.f);
            } else if (actv == 2) {
                if (res) {
                    if (v0) {
                        float2 r = *(const float2*)(res + (size_t)r0 * O + col);
                        o0.x += r.x; o0.y += r.y;
                    }
                    if (v1) {
                        float2 r = *(const float2*)(res + (size_t)r1 * O + col);
                        o1.x += r.x; o1.y += r.y;
                    }
                }
                o0.x = (o0.x > 0.f) ? o0.x : 0.01f * o0.x;
                o0.y = (o0.y > 0.f) ? o0.y : 0.01f * o0.y;
                o1.x = (o1.x > 0.f) ? o1.x : 0.01f * o1.x;
                o1.y = (o1.y > 0.f) ? o1.y : 0.01f * o1.y;
            }
            if (hout) {
                __half* Ch = (__half*)Cout;
                if (v0) *(__half2*)(Ch + (size_t)r0 * O + col) =
                            __floats2half2_rn(o0.x, o0.y);
                if (v1) *(__half2*)(Ch + (size_t)r1 * O + col) =
                            __floats2half2_rn(o1.x, o1.y);
            } else {
                float* Cf = (float*)Cout;
                if (v0) *(float2*)(Cf + (size_t)r0 * O + col) = o0;
                if (v1) *(float2*)(Cf + (size_t)r1 * O + col) = o1;
            }
        }
    }
}

// ---------------------------------------------------------------------------
// Fused 2-layer MLP (unchanged from R14).
// ---------------------------------------------------------------------------
__device__ __forceinline__ void mlp2_issueB(
    const __half* __restrict__ W, int strW, int wrow0, int kloc,
    int tid, uint32_t sbase, int stage)
{
    uint32_t so = sbase + stage * STG_B;
#pragma unroll
    for (int i = 0; i < 2; i++) {
        int id = tid + 256 * i;
        int row = id >> 2, cc = id & 3;
        const __half* src = W + (size_t)(wrow0 + row) * strW + kloc + cc * 8;
        cp_async16(so + OP_B + (row * ASTH + cc * 8) * 2, src, 16);
    }
    asm volatile("cp.async.commit_group;");
}

__global__ __launch_bounds__(256, 1) void mlp2_kernel(
    const __half* __restrict__ A,
    const __half* __restrict__ W1t, const float* __restrict__ b1,
    const __half* __restrict__ W2t, const float* __restrict__ b2,
    __half* __restrict__ Cout, int M, int K1, int O1, int O2)
{
    extern __shared__ float dsm[];
    uint32_t sb = smem_u32(dsm);
    __half* Sint = (__half*)((char*)dsm + NSTG * STG_B);
    uint32_t sintu = sb + NSTG * STG_B;

    int tid = threadIdx.x, lane = tid & 31, wid = tid >> 5;
    int bm = blockIdx.x * 128;
    int wm = wid & 1, wn = wid >> 1;
    int gid = lane >> 2, tig = lane & 3;

    int aRow = wm * 64 + ((lane >> 3) & 1) * 8 + (lane & 7);
    int aCol = (lane >> 4) * 8;
    int bRow = wn * 32 + ((lane >> 4) & 1) * 8 + (lane & 7);
    int bCol = ((lane >> 3) & 1) * 8;
    uint32_t aOff = (uint32_t)(aRow * ASTH + aCol) * 2;
    uint32_t bOff = OP_B + (uint32_t)(bRow * ASTH + bCol) * 2;
    uint32_t aOff2 = (uint32_t)(aRow * SINT + aCol) * 2;

    int nk1 = K1 / 32;
    for (int c1 = 0; c1 < O1 / 128; c1++) {
        float c[4][4][4];
#pragma unroll
        for (int mt = 0; mt < 4; mt++)
#pragma unroll
            for (int nt = 0; nt < 4; nt++)
#pragma unroll
                for (int q = 0; q < 4; q++) c[mt][nt][q] = 0.f;

        auto issue1 = [&](int kt, int stage) {
            uint32_t so = sb + stage * STG_B;
            int kloc = kt * 32;
#pragma unroll
            for (int i = 0; i < 2; i++) {
                int id = tid + 256 * i;
                int row = id >> 2, cc = id & 3;
                const __half* src = A + (size_t)(bm + row) * K1 + kloc + cc * 8;
                cp_async16(so + (row * ASTH + cc * 8) * 2, src,
                           (bm + row) < M ? 16 : 0);
            }
#pragma unroll
            for (int i = 0; i < 2; i++) {
                int id = tid + 256 * i;
                int row = id >> 2, cc = id & 3;
                const __half* src =
                    W1t + (size_t)(c1 * 128 + row) * K1 + kloc + cc * 8;
                cp_async16(so + OP_B + (row * ASTH + cc * 8) * 2, src, 16);
            }
            asm volatile("cp.async.commit_group;");
        };

        issue1(0, 0);
        issue1(1, 1);
        for (int kt = 0; kt < nk1; kt++) {
            int s = kt & 3;
            if (kt + 2 < nk1) {
                issue1(kt + 2, (kt + 2) & 3);
                asm volatile("cp.async.wait_group 2;");
            } else if (kt + 1 < nk1) {
                asm volatile("cp.async.wait_group 1;");
            } else {
                asm volatile("cp.async.wait_group 0;");
            }
            __syncthreads();

            uint32_t sAddr = sb + s * STG_B;
#pragma unroll
            for (int ks = 0; ks < 2; ks++) {
                uint32_t kOff = (uint32_t)(ks * 16) * 2;
                uint32_t af[4][4];
#pragma unroll
                for (int mt = 0; mt < 4; mt++)
                    LDSM_X4(af[mt][0], af[mt][1], af[mt][2], af[mt][3],
                            sAddr + aOff + (uint32_t)(mt * 16 * ASTH) * 2 + kOff);
                uint32_t bf[4][2];
#pragma unroll
                for (int nt2 = 0; nt2 < 2; nt2++)
                    LDSM_X4(bf[2 * nt2][0], bf[2 * nt2][1],
                            bf[2 * nt2 + 1][0], bf[2 * nt2 + 1][1],
                            sAddr + bOff + (uint32_t)(nt2 * 16 * ASTH) * 2 + kOff);
#pragma unroll
                for (int mt = 0; mt < 4; mt++)
#pragma unroll
                    for (int nt = 0; nt < 4; nt++)
                        MMA_F16(c[mt][nt], af[mt][0], af[mt][1], af[mt][2],
                                af[mt][3], bf[nt][0], bf[nt][1]);
            }
        }

#pragma unroll
        for (int mt = 0; mt < 4; mt++) {
            int lr0 = wm * 64 + mt * 16 + gid;
            int lr1 = lr0 + 8;
#pragma unroll
            for (int nt = 0; nt < 4; nt++) {
                int col = c1 * 128 + wn * 32 + nt * 8 + tig * 2;
                float2 bb = *(const float2*)(b1 + col);
                float o00 = fmaxf(c[mt][nt][0] + bb.x, 0.f);
                float o01 = fmaxf(c[mt][nt][1] + bb.y, 0.f);
                float o10 = fmaxf(c[mt][nt][2] + bb.x, 0.f);
                float o11 = fmaxf(c[mt][nt][3] + bb.y, 0.f);
                *(__half2*)(Sint + lr0 * SINT + col) = __floats2half2_rn(o00, o01);
                *(__half2*)(Sint + lr1 * SINT + col) = __floats2half2_rn(o10, o11);
            }
        }
        __syncthreads();
    }

    int nk2 = O1 / 32;
    for (int c2 = 0; c2 < O2 / 128; c2++) {
        float c[4][4][4];
#pragma unroll
        for (int mt = 0; mt < 4; mt++)
#pragma unroll
            for (int nt = 0; nt < 4; nt++)
#pragma unroll
                for (int q = 0; q < 4; q++) c[mt][nt][q] = 0.f;

        mlp2_issueB(W2t, O1, c2 * 128, 0, tid, sb, 0);
        mlp2_issueB(W2t, O1, c2 * 128, 32, tid, sb, 1);
        for (int kt = 0; kt < nk2; kt++) {
            int s = kt & 3;
            if (kt + 2 < nk2) {
                mlp2_issueB(W2t, O1, c2 * 128, (kt + 2) * 32, tid, sb, (kt + 2) & 3);
                asm volatile("cp.async.wait_group 2;");
            } else if (kt + 1 < nk2) {
                asm volatile("cp.async.wait_group 1;");
            } else {
                asm volatile("cp.async.wait_group 0;");
            }
            __syncthreads();

            uint32_t sAddr = sb + s * STG_B;
#pragma unroll
            for (int ks = 0; ks < 2; ks++) {
                uint32_t kBase = (uint32_t)(kt * 32 + ks * 16) * 2;
                uint32_t af[4][4];
#pragma unroll
                for (int mt = 0; mt < 4; mt++)
                    LDSM_X4(af[mt][0], af[mt][1], af[mt][2], af[mt][3],
                            sintu + aOff2 + (uint32_t)(mt * 16 * SINT) * 2 + kBase);
                uint32_t kOff = (uint32_t)(ks * 16) * 2;
                uint32_t bf[4][2];
#pragma unroll
                for (int nt2 = 0; nt2 < 2; nt2++)
                    LDSM_X4(bf[2 * nt2][0], bf[2 * nt2][1],
                            bf[2 * nt2 + 1][0], bf[2 * nt2 + 1][1],
                            sAddr + bOff + (uint32_t)(nt2 * 16 * ASTH) * 2 + kOff);
#pragma unroll
                for (int mt = 0; mt < 4; mt++)
#pragma unroll
                    for (int nt = 0; nt < 4; nt++)
                        MMA_F16(c[mt][nt], af[mt][0], af[mt][1], af[mt][2],
                                af[mt][3], bf[nt][0], bf[nt][1]);
            }
        }

#pragma unroll
        for (int mt = 0; mt < 4; mt++) {
            int r0 = bm + wm * 64 + mt * 16 + gid;
            int r1 = r0 + 8;
            bool v0 = r0 < M, v1 = r1 < M;
#pragma unroll
            for (int nt = 0; nt < 4; nt++) {
                int col = c2 * 128 + wn * 32 + nt * 8 + tig * 2;
                float2 bb = *(const float2*)(b2 + col);
                if (v0)
                    *(__half2*)(Cout + (size_t)r0 * O2 + col) =
                        __floats2half2_rn(c[mt][nt][0] + bb.x,
                                          c[mt][nt][1] + bb.y);
                if (v1)
                    *(__half2*)(Cout + (size_t)r1 * O2 + col) =
                        __floats2half2_rn(c[mt][nt][2] + bb.x,
                                          c[mt][nt][3] + bb.y);
            }
        }
        __syncthreads();
    }
}

// ---------------------------------------------------------------------------
// LSE + attentive pool. R14 math, software-pipelined gathers:
// while computing point p, prefetch p+1's neighbor indices (before hidden)
// and p+1's coords (after the mma); feats load hoisted above the mma.
// ---------------------------------------------------------------------------
#define LSTR 136

__global__ __launch_bounds__(256) void lse_mma_kernel(
    const float* __restrict__ coords, const int* __restrict__ nidx,
    const __half* __restrict__ feats,
    const float* __restrict__ W1, const float* __restrict__ B1,
    const float* __restrict__ W2, const float* __restrict__ B2,
    __half* __restrict__ outF, int N)
{
    __shared__ float sW1[640];
    __shared__ float sB1[64];
    __shared__ float sB2[128];
    __shared__ float sW2[64 * LSTR];

    int tid = threadIdx.x, lane = tid & 31, wid = tid >> 5;
    int gid = lane >> 2, tig = lane & 3;

    for (int i = tid; i < 640; i += 256) sW1[i] = W1[i];
    if (tid < 64) sB1[tid] = B1[tid];
    if (tid < 128) sB2[tid] = B2[tid];
    for (int i = tid; i < 8192; i += 256) {
        int k = i >> 7, ch = i & 127;
        sW2[k * LSTR + ch] = to_tf32(W2[i]);
    }
    __syncthreads();

    int nbase = blockIdx.x * 64 + wid * 8;
    if (nbase >= N) return;

    // preload point 0 gathers
    int ib0 = nidx[nbase * KNBR + gid];
    int ib1 = nidx[nbase * KNBR + gid + 8];
    float ox = coords[nbase * 3], oy = coords[nbase * 3 + 1], oz = coords[nbase * 3 + 2];
    float ax = coords[ib0 * 3], ay = coords[ib0 * 3 + 1], az = coords[ib0 * 3 + 2];
    float bx = coords[ib1 * 3], by = coords[ib1 * 3 + 1], bz = coords[ib1 * 3 + 2];

    for (int p = 0; p < 8; p++) {
        int n = nbase + p;
        bool hasNext = (p < 7) && (n + 1 < N);

        // prefetch next point's neighbor indices (independent loads)
        int jb0 = 0, jb1 = 0;
        if (hasNext) {
            jb0 = nidx[(n + 1) * KNBR + gid];
            jb1 = nidx[(n + 1) * KNBR + gid + 8];
        }

        // feats load hoisted: latency overlaps hidden + mma below
        const __half2* fp = (const __half2*)(feats + (size_t)n * 128);
        __half2 fh0 = fp[2 * lane], fh1 = fp[2 * lane + 1];

        float arx = ox - ax, ary = oy - ay, arz = oz - az;
        float brx = ox - bx, bry = oy - by, brz = oz - bz;
        float ad = sqrtf(arx * arx + ary * ary + arz * arz);
        float bd = sqrtf(brx * brx + bry * bry + brz * brz);
        float ca[10] = {ox, oy, oz, ax, ay, az, arx, ary, arz, ad};
        float cb[10] = {ox, oy, oz, bx, by, bz, brx, bry, brz, bd};

        uint32_t hb0[16], hb1[16];
#pragma unroll
        for (int j = 0; j < 16; j++) {
            int ch = tig + 4 * j;
            float h0 = sB1[ch], h1 = h0;
#pragma unroll
            for (int i = 0; i < 10; i++) {
                float w = sW1[i * 64 + ch];
                h0 = fmaf(ca[i], w, h0);
                h1 = fmaf(cb[i], w, h1);
            }
            hb0[j] = __float_as_uint(to_tf32(fmaxf(h0, 0.f)));
            hb1[j] = __float_as_uint(to_tf32(fmaxf(h1, 0.f)));
        }

        float c_[8][2][4];
#pragma unroll
        for (int mt = 0; mt < 8; mt++)
#pragma unroll
            for (int nt = 0; nt < 2; nt++)
#pragma unroll
                for (int q = 0; q < 4; q++) c_[mt][nt][q] = 0.f;

#pragma unroll
        for (int s = 0; s < 8; s++) {
            uint32_t b00 = hb0[2 * s], b01 = hb0[2 * s + 1];
            uint32_t b10 = hb1[2 * s], b11 = hb1[2 * s + 1];
            const float* r0 = &sW2[(8 * s + tig) * LSTR];
            const float* r1 = &sW2[(8 * s + tig + 4) * LSTR];
#pragma unroll
            for (int mt = 0; mt < 8; mt++) {
                int cb0 = 16 * mt + gid;
                uint32_t a0 = __float_as_uint(r0[cb0]);
                uint32_t a1 = __float_as_uint(r0[cb0 + 8]);
                uint32_t a2 = __float_as_uint(r1[cb0]);
                uint32_t a3 = __float_as_uint(r1[cb0 + 8]);
                MMA_TF32(c_[mt][0], a0, a1, a2, a3, b00, b01);
                MMA_TF32(c_[mt][1], a0, a1, a2, a3, b10, b11);
            }
        }

        // prefetch next point's coords (indices have landed by now)
        float nox = 0.f, noy = 0.f, noz = 0.f;
        float nax = 0.f, nay = 0.f, naz = 0.f;
        float nbx = 0.f, nby = 0.f, nbz = 0.f;
        if (hasNext) {
            nox = coords[(n + 1) * 3];     noy = coords[(n + 1) * 3 + 1];
            noz = coords[(n + 1) * 3 + 2];
            nax = coords[jb0 * 3]; nay = coords[jb0 * 3 + 1]; naz = coords[jb0 * 3 + 2];
            nbx = coords[jb1 * 3]; nby = coords[jb1 * 3 + 1]; nbz = coords[jb1 * 3 + 2];
        }

#pragma unroll
        for (int mt = 0; mt < 8; mt++) {
            float bb0 = sB2[16 * mt + gid], bb1 = sB2[16 * mt + gid + 8];
#pragma unroll
            for (int nt = 0; nt < 2; nt++) {
                c_[mt][nt][0] += bb0; c_[mt][nt][1] += bb0;
                c_[mt][nt][2] += bb1; c_[mt][nt][3] += bb1;
            }
        }

        float4 f4 = make_float4(__low2float(fh0), __high2float(fh0),
                                __low2float(fh1), __high2float(fh1));
        float ef[4] = {__expf(f4.x), __expf(f4.y), __expf(f4.z), __expf(f4.w)};
        float sf = ef[0] + ef[1] + ef[2] + ef[3];
#pragma unroll
        for (int o = 16; o > 0; o >>= 1)
            sf += __shfl_xor_sync(0xffffffffu, sf, o);

        float ov[8][2];
#pragma unroll
        for (int mt = 0; mt < 8; mt++) { ov[mt][0] = 0.f; ov[mt][1] = 0.f; }
        float Tl = 0.f;

#pragma unroll
        for (int j = 0; j < 4; j++) {
            int nt = j >> 1, q = j & 1;
            float e0[8], e1[8], s = 0.f;
#pragma unroll
            for (int mt = 0; mt < 8; mt++) {
                e0[mt] = __expf(c_[mt][nt][q]);
                e1[mt] = __expf(c_[mt][nt][q + 2]);
                s += e0[mt] + e1[mt];
            }
#pragma unroll
            for (int o = 4; o <= 16; o <<= 1)
                s += __shfl_xor_sync(0xffffffffu, s, o);
            float inv = 1.f / (s + sf);
            Tl += inv;
#pragma unroll
            for (int mt = 0; mt < 8; mt++) {
                ov[mt][0] = fmaf(e0[mt] * inv, c_[mt][nt][q], ov[mt][0]);
                ov[mt][1] = fmaf(e1[mt] * inv, c_[mt][nt][q + 2], ov[mt][1]);
            }
        }
        Tl += __shfl_xor_sync(0xffffffffu, Tl, 1);
        Tl += __shfl_xor_sync(0xffffffffu, Tl, 2);

#pragma unroll
        for (int mt = 0; mt < 8; mt++) {
#pragma unroll
            for (int cs = 0; cs < 2; cs++) {
                ov[mt][cs] += __shfl_xor_sync(0xffffffffu, ov[mt][cs], 1);
                ov[mt][cs] += __shfl_xor_sync(0xffffffffu, ov[mt][cs], 2);
            }
        }

        __half* po = outF + (size_t)n * 256;
#pragma unroll
        for (int t = 0; t < 2; t++) {
            int mt = 2 * tig + t;
            po[16 * mt + gid]     = __float2half_rn(ov[mt][0]);
            po[16 * mt + gid + 8] = __float2half_rn(ov[mt][1]);
        }
        __half2* gp = (__half2*)(po + 128 + 4 * lane);
        gp[0] = __floats2half2_rn(f4.x * ef[0] * Tl, f4.y * ef[1] * Tl);
        gp[1] = __floats2half2_rn(f4.z * ef[2] * Tl, f4.w * ef[3] * Tl);

        if (!hasNext) break;
        ib0 = jb0; ib1 = jb1;
        ox = nox; oy = noy; oz = noz;
        ax = nax; ay = nay; az = naz;
        bx = nbx; by = nby; bz = nbz;
    }
}

// ---------------------------------------------------------------------------
extern "C" void kernel_launch(void* const* d_in, const int* in_sizes, int n_in,
                              void* d_out, int out_size)
{
    const float* coords   = (const float*)d_in[0];
    const float* features = (const float*)d_in[1];
    const int*   nidx     = (const int*)d_in[2];
    const float* m1W1 = (const float*)d_in[3];  const float* m1b1 = (const float*)d_in[4];
    const float* m1W2 = (const float*)d_in[5];  const float* m1b2 = (const float*)d_in[6];
    const float* m2W1 = (const float*)d_in[7];  const float* m2b1 = (const float*)d_in[8];
    const float* m2W2 = (const float*)d_in[9];  const float* m2b2 = (const float*)d_in[10];
    const float* m3W1 = (const float*)d_in[11]; const float* m3b1 = (const float*)d_in[12];
    const float* m3W2 = (const float*)d_in[13]; const float* m3b2 = (const float*)d_in[14];
    const float* l1W1 = (const float*)d_in[15]; const float* l1b1 = (const float*)d_in[16];
    const float* l1W2 = (const float*)d_in[17]; const float* l1b2 = (const float*)d_in[18];
    const float* l2W1 = (const float*)d_in[19]; const float* l2b1 = (const float*)d_in[20];
    const float* l2W2 = (const float*)d_in[21]; const float* l2b2 = (const float*)d_in[22];
    const float* p1W1 = (const float*)d_in[23]; const float* p1b1 = (const float*)d_in[24];
    const float* p1W2 = (const float*)d_in[25]; const float* p1b2 = (const float*)d_in[26];
    const float* p2W1 = (const float*)d_in[27]; const float* p2b1 = (const float*)d_in[28];
    const float* p2W2 = (const float*)d_in[29]; const float* p2b2 = (const float*)d_in[30];
    float* out = (float*)d_out;

    int N = in_sizes[0] / 3;

    __half *hA, *hB, *hF, *hW, *hD;
    float* bufC;
    cudaGetSymbolAddress((void**)&hA, g_hA);
    cudaGetSymbolAddress((void**)&hB, g_hB);
    cudaGetSymbolAddress((void**)&bufC, g_bufC);
    cudaGetSymbolAddress((void**)&hF, g_hF);
    cudaGetSymbolAddress((void**)&hW, g_hW);
    cudaGetSymbolAddress((void**)&hD, g_hD);

    static cudaStream_t s2 = nullptr;
    static cudaEvent_t ev0 = nullptr, evW = nullptr, evF = nullptr, evM3 = nullptr;
    if (!s2) {
        cudaFuncSetAttribute(hgemm_kernel,
                             cudaFuncAttributeMaxDynamicSharedMemorySize,
                             HGEMM_SMEM);
        cudaFuncSetAttribute(mlp2_kernel,
                             cudaFuncAttributeMaxDynamicSharedMemorySize,
                             MLP2_SMEM);
        cudaStreamCreateWithFlags(&s2, cudaStreamNonBlocking);
        cudaEventCreateWithFlags(&ev0, cudaEventDisableTiming);
        cudaEventCreateWithFlags(&evW, cudaEventDisableTiming);
        cudaEventCreateWithFlags(&evF, cudaEventDisableTiming);
        cudaEventCreateWithFlags(&evM3, cudaEventDisableTiming);
    }

    // Weight layout in g_hW (halves):
    const int oM1W1 = 0;        // 128x128
    const int oM1W2 = 16384;    // 128x128
    const int oM2W1 = 32768;    // 384x256
    const int oM3W1 = 131072;   // 256x128
    const int oP1W1 = 163840;   // 256x256
    const int oP1W2 = 229376;   // 128x256
    const int oP2W1 = 262144;   // 256x256
    const int oP2W2 = 327680;   // 256x256
    const int oWCAT = 393216;   // 512x640  ([m2W2 | m3W2] per output row)

    WPackT wp;
    auto setw = [&](int i, const float* s, int Kd, int Od, int ld, int coff, int off) {
        wp.s[i] = s; wp.Kd[i] = Kd; wp.Od[i] = Od;
        wp.ld[i] = ld; wp.coff[i] = coff; wp.off[i] = off;
    };
    setw(0, m1W1, 128, 128, 128, 0, oM1W1);
    setw(1, m1W2, 128, 128, 128, 0, oM1W2);
    setw(2, m2W1, 256, 384, 256, 0, oM2W1);
    setw(3, m2W2, 384, 512, 640, 0, oWCAT);
    setw(4, m3W1, 128, 256, 128, 0, oM3W1);
    setw(5, m3W2, 256, 512, 640, 384, oWCAT);
    setw(6, p1W1, 256, 256, 256, 0, oP1W1);
    setw(7, p1W2, 256, 128, 256, 0, oP1W2);
    setw(8, p2W1, 256, 256, 256, 0, oP2W1);
    setw(9, p2W2, 256, 256, 256, 0, oP2W2);

    dim3 gblk(256), lblk(256);
    auto grid = [&](int M, int O) { return dim3((M + 127) / 128, O / 128); };
    dim3 mgrid((N + 127) / 128, 1);
    int lse_grid = (N + 63) / 64;
    int SB = HGEMM_SMEM;

    // ---- fork: weights round on s2, features round on legacy ----
    cudaEventRecord(ev0, 0);
    cudaStreamWaitEvent(s2, ev0, 0);
    round_weightsT_kernel<<<dim3(192, 10), 1024, 0, s2>>>(wp, hW);
    cudaEventRecord(evW, s2);

    round_feat_kernel<<<(N * 128 + 1023) / 1024, 1024>>>(features, hF, N * 128);
    cudaEventRecord(evF, 0);

    // ---- side stream: m3 hidden only (features -> 256 half) ----
    cudaStreamWaitEvent(s2, evF, 0);
    hgemm_kernel<<<grid(N, 256), gblk, SB, s2>>>(
        hF, nullptr, hW + oM3W1, m3b1, nullptr, nullptr, hD, N, 128, 0, 256, 9);
    cudaEventRecord(evM3, s2);

    // ---- main chain (legacy stream), waits for weights ----
    cudaStreamWaitEvent(0, evW, 0);
    // m1 fused: 128 -> relu 128 -> 128 (half)
    mlp2_kernel<<<mgrid, gblk, MLP2_SMEM>>>(
        hF, hW + oM1W1, m1b1, hW + oM1W2, m1b2, hB, N, 128, 128, 128);
    // lse1 -> (N,256) half
    lse_mma_kernel<<<lse_grid, lblk>>>(coords, nidx, hB, l1W1, l1b1, l1W2, l1b2, hA, N);
    // p1 fused: 256 -> relu 256 -> 128 (half)
    mlp2_kernel<<<mgrid, gblk, MLP2_SMEM>>>(
        hA, hW + oP1W1, p1b1, hW + oP1W2, p1b2, hB, N, 256, 256, 128);
    // lse2 -> (N,256) half
    lse_mma_kernel<<<lse_grid, lblk>>>(coords, nidx, hB, l2W1, l2b1, l2W2, l2b2, hA, N);
    // p2 fused: 256 -> relu 256 -> 256 (half)
    mlp2_kernel<<<mgrid, gblk, MLP2_SMEM>>>(
        hA, hW + oP2W1, p2b1, hW + oP2W2, p2b2, hB, N, 256, 256, 256);
    // m2 hidden: 256 -> 384 (relu, half)
    hgemm_kernel<<<grid(N, 384), gblk, SB>>>(
        hB, nullptr, hW + oM2W1, m2b1, nullptr, nullptr, hA, N, 256, 0, 384, 9);
    // FUSED final: leaky( [m2_hidden | m3_hidden] @ [m2W2; m3W2] + b2 + b3 )
    cudaStreamWaitEvent(0, evM3, 0);
    hgemm_kernel<<<grid(N, 512), gblk, SB>>>(
        hA, hD, hW + oWCAT, m2b2, m3b2, nullptr, out, N, 384, 256, 512, 2);
}

// round 17
// speedup vs baseline: 1.4699x; 1.4699x over previous
#include <cuda_runtime.h>
#include <cuda_fp16.h>
#include <math.h>
#include <stdint.h>

#define NMAX 100000
#define KNBR 16

// Scratch (static __device__ — allocation-guard safe)
__device__ __half g_hA[NMAX * 384];
__device__ __half g_hB[NMAX * 256];
__device__ float  g_bufC[NMAX * 512];
__device__ __half g_hF[NMAX * 128];     // half features
__device__ __half g_hW[720896];         // half transposed weights (incl. [512][640] concat)
__device__ __half g_hD[NMAX * 256];     // m3 hidden (side stream)

__device__ __forceinline__ uint32_t smem_u32(const void* p) {
    uint32_t a;
    asm("{ .reg .u64 t; cvta.to.shared.u64 t, %1; cvt.u32.u64 %0, t; }"
        : "=r"(a) : "l"(p));
    return a;
}

__device__ __forceinline__ uint32_t h2_u32(__half2 h) {
    uint32_t u;
    memcpy(&u, &h, 4);
    return u;
}

__device__ __forceinline__ void cp_async16(uint32_t dst, const void* src, int szb) {
    asm volatile("cp.async.cg.shared.global [%0], [%1], 16, %2;"
                 :: "r"(dst), "l"(src), "r"(szb));
}

#define LDSM_X4(r0, r1, r2, r3, addr)                                         \
    asm volatile("ldmatrix.sync.aligned.m8n8.x4.shared.b16 {%0,%1,%2,%3}, [%4];" \
        : "=r"(r0), "=r"(r1), "=r"(r2), "=r"(r3) : "r"(addr))

#define MMA_F16(C, a0, a1, a2, a3, b0, b1)                                    \
    asm volatile(                                                             \
        "mma.sync.aligned.m16n8k16.row.col.f32.f16.f16.f32 "                  \
        "{%0,%1,%2,%3}, {%4,%5,%6,%7}, {%8,%9}, {%0,%1,%2,%3};"               \
        : "+f"((C)[0]), "+f"((C)[1]), "+f"((C)[2]), "+f"((C)[3])              \
        : "r"(a0), "r"(a1), "r"(a2), "r"(a3), "r"(b0), "r"(b1))

// ---------------------------------------------------------------------------
// Pre-round: weights -> half, transposed to [O][ld] with column offset.
// ---------------------------------------------------------------------------
struct WPackT {
    const float* s[10];
    int Kd[10];
    int Od[10];
    int ld[10];
    int coff[10];
    int off[10];
};

__global__ void round_weightsT_kernel(WPackT p, __half* dst) {
    int m = blockIdx.y;
    int i = blockIdx.x * blockDim.x + threadIdx.x;
    int Kd = p.Kd[m], Od = p.Od[m];
    if (i < Kd * Od) {
        int k = i / Od, o = i % Od;
        dst[p.off[m] + (size_t)o * p.ld[m] + p.coff[m] + k] =
            __float2half_rn(p.s[m][i]);
    }
}

__global__ void round_feat_kernel(const float* __restrict__ src,
                                  __half* __restrict__ dst, int n) {
    int i = blockIdx.x * blockDim.x + threadIdx.x;
    if (i < n) dst[i] = __float2half_rn(src[i]);
}

// ---------------------------------------------------------------------------
// Shared tiling constants
// ---------------------------------------------------------------------------
#define ASTH 40
#define AS_HL (128 * ASTH)
#define OP_B  (AS_HL * 2)
#define STG_B (2 * OP_B)
#define NSTG 4
#define HGEMM_SMEM (NSTG * STG_B)       // 81920
#define SINT 264
#define MLP2_SMEM (NSTG * STG_B + 128 * SINT * 2)   // 149504

// ---------------------------------------------------------------------------
// fp16 tensor-core GEMM (dual-A capable). Unchanged from R13/R14.
// ---------------------------------------------------------------------------
__device__ __forceinline__ void hgemm_issue2(
    const __half* __restrict__ Abase, int strideA, int kloc,
    const __half* __restrict__ Wt, int KW, int kw,
    int M, int bm, int bn, int tid, uint32_t sbase, int stage)
{
    uint32_t so = sbase + stage * STG_B;
#pragma unroll
    for (int i = 0; i < 2; i++) {
        int id = tid + 256 * i;
        int row = id >> 2, cc = id & 3;
        const __half* src = Abase + (size_t)(bm + row) * strideA + kloc + cc * 8;
        cp_async16(so + (row * ASTH + cc * 8) * 2, src, (bm + row) < M ? 16 : 0);
    }
#pragma unroll
    for (int i = 0; i < 2; i++) {
        int id = tid + 256 * i;
        int row = id >> 2, cc = id & 3;
        const __half* src = Wt + (size_t)(bn + row) * KW + kw + cc * 8;
        cp_async16(so + OP_B + (row * ASTH + cc * 8) * 2, src, 16);
    }
    asm volatile("cp.async.commit_group;");
}

__global__ __launch_bounds__(256, 2) void hgemm_kernel(
    const __half* __restrict__ A, const __half* __restrict__ A2,
    const __half* __restrict__ Wt,
    const float* __restrict__ bias, const float* __restrict__ bias2,
    const float* __restrict__ res,
    void* __restrict__ Cout, int M, int K, int K2, int O, int act)
{
    extern __shared__ float dsm[];
    uint32_t sb = smem_u32(dsm);

    int tid = threadIdx.x, lane = tid & 31, wid = tid >> 5;
    int bm = blockIdx.x * 128, bn = blockIdx.y * 128;
    int wm = wid & 1, wn = wid >> 1;
    int gid = lane >> 2, tig = lane & 3;
    bool hout = (act & 8) != 0;
    int actv = act & 3;
    int KW = K + K2;
    int nk1 = K / 32, nk = KW / 32;

    int aRow = wm * 64 + ((lane >> 3) & 1) * 8 + (lane & 7);
    int aCol = (lane >> 4) * 8;
    int bRow = wn * 32 + ((lane >> 4) & 1) * 8 + (lane & 7);
    int bCol = ((lane >> 3) & 1) * 8;
    uint32_t aOff = (uint32_t)(aRow * ASTH + aCol) * 2;
    uint32_t bOff = OP_B + (uint32_t)(bRow * ASTH + bCol) * 2;

    float c[4][4][4];
#pragma unroll
    for (int mt = 0; mt < 4; mt++)
#pragma unroll
        for (int nt = 0; nt < 4; nt++)
#pragma unroll
            for (int q = 0; q < 4; q++) c[mt][nt][q] = 0.f;

    auto issue = [&](int kt, int stage) {
        const __half* Ab; int strA, kloc;
        if (kt < nk1) { Ab = A;  strA = K;  kloc = kt * 32; }
        else          { Ab = A2; strA = K2; kloc = (kt - nk1) * 32; }
        hgemm_issue2(Ab, strA, kloc, Wt, KW, kt * 32, M, bm, bn, tid, sb, stage);
    };

    issue(0, 0);
    issue(1, 1);

    for (int kt = 0; kt < nk; kt++) {
        int s = kt & 3;
        if (kt + 2 < nk) {
            issue(kt + 2, (kt + 2) & 3);
            asm volatile("cp.async.wait_group 2;");
        } else if (kt + 1 < nk) {
            asm volatile("cp.async.wait_group 1;");
        } else {
            asm volatile("cp.async.wait_group 0;");
        }
        __syncthreads();

        uint32_t sAddr = sb + s * STG_B;
#pragma unroll
        for (int ks = 0; ks < 2; ks++) {
            uint32_t kOff = (uint32_t)(ks * 16) * 2;
            uint32_t af[4][4];
#pragma unroll
            for (int mt = 0; mt < 4; mt++)
                LDSM_X4(af[mt][0], af[mt][1], af[mt][2], af[mt][3],
                        sAddr + aOff + (uint32_t)(mt * 16 * ASTH) * 2 + kOff);
            uint32_t bf[4][2];
#pragma unroll
            for (int nt2 = 0; nt2 < 2; nt2++)
                LDSM_X4(bf[2 * nt2][0], bf[2 * nt2][1],
                        bf[2 * nt2 + 1][0], bf[2 * nt2 + 1][1],
                        sAddr + bOff + (uint32_t)(nt2 * 16 * ASTH) * 2 + kOff);
#pragma unroll
            for (int mt = 0; mt < 4; mt++)
#pragma unroll
                for (int nt = 0; nt < 4; nt++)
                    MMA_F16(c[mt][nt], af[mt][0], af[mt][1], af[mt][2],
                            af[mt][3], bf[nt][0], bf[nt][1]);
        }
    }

#pragma unroll
    for (int mt = 0; mt < 4; mt++) {
        int r0 = bm + wm * 64 + mt * 16 + gid;
        int r1 = r0 + 8;
        bool v0 = r0 < M, v1 = r1 < M;
#pragma unroll
        for (int nt = 0; nt < 4; nt++) {
            int col = bn + wn * 32 + nt * 8 + tig * 2;
            float2 bb = *(const float2*)(bias + col);
            if (bias2) {
                float2 b2 = *(const float2*)(bias2 + col);
                bb.x += b2.x; bb.y += b2.y;
            }
            float2 o0 = make_float2(c[mt][nt][0] + bb.x, c[mt][nt][1] + bb.y);
            float2 o1 = make_float2(c[mt][nt][2] + bb.x, c[mt][nt][3] + bb.y);
            if (actv == 1) {
                o0.x = fmaxf(o0.x, 0.f); o0.y = fmaxf(o0.y, 0.f);
                o1.x = fmaxf(o1.x, 0.f); o1.y = fmaxf(o1.y, 0.f);
            } else if (actv == 2) {
                if (res) {
                    if (v0) {
                        float2 r = *(const float2*)(res + (size_t)r0 * O + col);
                        o0.x += r.x; o0.y += r.y;
                    }
                    if (v1) {
                        float2 r = *(const float2*)(res + (size_t)r1 * O + col);
                        o1.x += r.x; o1.y += r.y;
                    }
                }
                o0.x = (o0.x > 0.f) ? o0.x : 0.01f * o0.x;
                o0.y = (o0.y > 0.f) ? o0.y : 0.01f * o0.y;
                o1.x = (o1.x > 0.f) ? o1.x : 0.01f * o1.x;
                o1.y = (o1.y > 0.f) ? o1.y : 0.01f * o1.y;
            }
            if (hout) {
                __half* Ch = (__half*)Cout;
                if (v0) *(__half2*)(Ch + (size_t)r0 * O + col) =
                            __floats2half2_rn(o0.x, o0.y);
                if (v1) *(__half2*)(Ch + (size_t)r1 * O + col) =
                            __floats2half2_rn(o1.x, o1.y);
            } else {
                float* Cf = (float*)Cout;
                if (v0) *(float2*)(Cf + (size_t)r0 * O + col) = o0;
                if (v1) *(float2*)(Cf + (size_t)r1 * O + col) = o1;
            }
        }
    }
}

// ---------------------------------------------------------------------------
// Fused 2-layer MLP (unchanged from R14).
// ---------------------------------------------------------------------------
__device__ __forceinline__ void mlp2_issueB(
    const __half* __restrict__ W, int strW, int wrow0, int kloc,
    int tid, uint32_t sbase, int stage)
{
    uint32_t so = sbase + stage * STG_B;
#pragma unroll
    for (int i = 0; i < 2; i++) {
        int id = tid + 256 * i;
        int row = id >> 2, cc = id & 3;
        const __half* src = W + (size_t)(wrow0 + row) * strW + kloc + cc * 8;
        cp_async16(so + OP_B + (row * ASTH + cc * 8) * 2, src, 16);
    }
    asm volatile("cp.async.commit_group;");
}

__global__ __launch_bounds__(256, 1) void mlp2_kernel(
    const __half* __restrict__ A,
    const __half* __restrict__ W1t, const float* __restrict__ b1,
    const __half* __restrict__ W2t, const float* __restrict__ b2,
    __half* __restrict__ Cout, int M, int K1, int O1, int O2)
{
    extern __shared__ float dsm[];
    uint32_t sb = smem_u32(dsm);
    __half* Sint = (__half*)((char*)dsm + NSTG * STG_B);
    uint32_t sintu = sb + NSTG * STG_B;

    int tid = threadIdx.x, lane = tid & 31, wid = tid >> 5;
    int bm = blockIdx.x * 128;
    int wm = wid & 1, wn = wid >> 1;
    int gid = lane >> 2, tig = lane & 3;

    int aRow = wm * 64 + ((lane >> 3) & 1) * 8 + (lane & 7);
    int aCol = (lane >> 4) * 8;
    int bRow = wn * 32 + ((lane >> 4) & 1) * 8 + (lane & 7);
    int bCol = ((lane >> 3) & 1) * 8;
    uint32_t aOff = (uint32_t)(aRow * ASTH + aCol) * 2;
    uint32_t bOff = OP_B + (uint32_t)(bRow * ASTH + bCol) * 2;
    uint32_t aOff2 = (uint32_t)(aRow * SINT + aCol) * 2;

    int nk1 = K1 / 32;
    for (int c1 = 0; c1 < O1 / 128; c1++) {
        float c[4][4][4];
#pragma unroll
        for (int mt = 0; mt < 4; mt++)
#pragma unroll
            for (int nt = 0; nt < 4; nt++)
#pragma unroll
                for (int q = 0; q < 4; q++) c[mt][nt][q] = 0.f;

        auto issue1 = [&](int kt, int stage) {
            uint32_t so = sb + stage * STG_B;
            int kloc = kt * 32;
#pragma unroll
            for (int i = 0; i < 2; i++) {
                int id = tid + 256 * i;
                int row = id >> 2, cc = id & 3;
                const __half* src = A + (size_t)(bm + row) * K1 + kloc + cc * 8;
                cp_async16(so + (row * ASTH + cc * 8) * 2, src,
                           (bm + row) < M ? 16 : 0);
            }
#pragma unroll
            for (int i = 0; i < 2; i++) {
                int id = tid + 256 * i;
                int row = id >> 2, cc = id & 3;
                const __half* src =
                    W1t + (size_t)(c1 * 128 + row) * K1 + kloc + cc * 8;
                cp_async16(so + OP_B + (row * ASTH + cc * 8) * 2, src, 16);
            }
            asm volatile("cp.async.commit_group;");
        };

        issue1(0, 0);
        issue1(1, 1);
        for (int kt = 0; kt < nk1; kt++) {
            int s = kt & 3;
            if (kt + 2 < nk1) {
                issue1(kt + 2, (kt + 2) & 3);
                asm volatile("cp.async.wait_group 2;");
            } else if (kt + 1 < nk1) {
                asm volatile("cp.async.wait_group 1;");
            } else {
                asm volatile("cp.async.wait_group 0;");
            }
            __syncthreads();

            uint32_t sAddr = sb + s * STG_B;
#pragma unroll
            for (int ks = 0; ks < 2; ks++) {
                uint32_t kOff = (uint32_t)(ks * 16) * 2;
                uint32_t af[4][4];
#pragma unroll
                for (int mt = 0; mt < 4; mt++)
                    LDSM_X4(af[mt][0], af[mt][1], af[mt][2], af[mt][3],
                            sAddr + aOff + (uint32_t)(mt * 16 * ASTH) * 2 + kOff);
                uint32_t bf[4][2];
#pragma unroll
                for (int nt2 = 0; nt2 < 2; nt2++)
                    LDSM_X4(bf[2 * nt2][0], bf[2 * nt2][1],
                            bf[2 * nt2 + 1][0], bf[2 * nt2 + 1][1],
                            sAddr + bOff + (uint32_t)(nt2 * 16 * ASTH) * 2 + kOff);
#pragma unroll
                for (int mt = 0; mt < 4; mt++)
#pragma unroll
                    for (int nt = 0; nt < 4; nt++)
                        MMA_F16(c[mt][nt], af[mt][0], af[mt][1], af[mt][2],
                                af[mt][3], bf[nt][0], bf[nt][1]);
            }
        }

#pragma unroll
        for (int mt = 0; mt < 4; mt++) {
            int lr0 = wm * 64 + mt * 16 + gid;
            int lr1 = lr0 + 8;
#pragma unroll
            for (int nt = 0; nt < 4; nt++) {
                int col = c1 * 128 + wn * 32 + nt * 8 + tig * 2;
                float2 bb = *(const float2*)(b1 + col);
                float o00 = fmaxf(c[mt][nt][0] + bb.x, 0.f);
                float o01 = fmaxf(c[mt][nt][1] + bb.y, 0.f);
                float o10 = fmaxf(c[mt][nt][2] + bb.x, 0.f);
                float o11 = fmaxf(c[mt][nt][3] + bb.y, 0.f);
                *(__half2*)(Sint + lr0 * SINT + col) = __floats2half2_rn(o00, o01);
                *(__half2*)(Sint + lr1 * SINT + col) = __floats2half2_rn(o10, o11);
            }
        }
        __syncthreads();
    }

    int nk2 = O1 / 32;
    for (int c2 = 0; c2 < O2 / 128; c2++) {
        float c[4][4][4];
#pragma unroll
        for (int mt = 0; mt < 4; mt++)
#pragma unroll
            for (int nt = 0; nt < 4; nt++)
#pragma unroll
                for (int q = 0; q < 4; q++) c[mt][nt][q] = 0.f;

        mlp2_issueB(W2t, O1, c2 * 128, 0, tid, sb, 0);
        mlp2_issueB(W2t, O1, c2 * 128, 32, tid, sb, 1);
        for (int kt = 0; kt < nk2; kt++) {
            int s = kt & 3;
            if (kt + 2 < nk2) {
                mlp2_issueB(W2t, O1, c2 * 128, (kt + 2) * 32, tid, sb, (kt + 2) & 3);
                asm volatile("cp.async.wait_group 2;");
            } else if (kt + 1 < nk2) {
                asm volatile("cp.async.wait_group 1;");
            } else {
                asm volatile("cp.async.wait_group 0;");
            }
            __syncthreads();

            uint32_t sAddr = sb + s * STG_B;
#pragma unroll
            for (int ks = 0; ks < 2; ks++) {
                uint32_t kBase = (uint32_t)(kt * 32 + ks * 16) * 2;
                uint32_t af[4][4];
#pragma unroll
                for (int mt = 0; mt < 4; mt++)
                    LDSM_X4(af[mt][0], af[mt][1], af[mt][2], af[mt][3],
                            sintu + aOff2 + (uint32_t)(mt * 16 * SINT) * 2 + kBase);
                uint32_t kOff = (uint32_t)(ks * 16) * 2;
                uint32_t bf[4][2];
#pragma unroll
                for (int nt2 = 0; nt2 < 2; nt2++)
                    LDSM_X4(bf[2 * nt2][0], bf[2 * nt2][1],
                            bf[2 * nt2 + 1][0], bf[2 * nt2 + 1][1],
                            sAddr + bOff + (uint32_t)(nt2 * 16 * ASTH) * 2 + kOff);
#pragma unroll
                for (int mt = 0; mt < 4; mt++)
#pragma unroll
                    for (int nt = 0; nt < 4; nt++)
                        MMA_F16(c[mt][nt], af[mt][0], af[mt][1], af[mt][2],
                                af[mt][3], bf[nt][0], bf[nt][1]);
            }
        }

#pragma unroll
        for (int mt = 0; mt < 4; mt++) {
            int r0 = bm + wm * 64 + mt * 16 + gid;
            int r1 = r0 + 8;
            bool v0 = r0 < M, v1 = r1 < M;
#pragma unroll
            for (int nt = 0; nt < 4; nt++) {
                int col = c2 * 128 + wn * 32 + nt * 8 + tig * 2;
                float2 bb = *(const float2*)(b2 + col);
                if (v0)
                    *(__half2*)(Cout + (size_t)r0 * O2 + col) =
                        __floats2half2_rn(c[mt][nt][0] + bb.x,
                                          c[mt][nt][1] + bb.y);
                if (v1)
                    *(__half2*)(Cout + (size_t)r1 * O2 + col) =
                        __floats2half2_rn(c[mt][nt][2] + bb.x,
                                          c[mt][nt][3] + bb.y);
            }
        }
        __syncthreads();
    }
}

// ---------------------------------------------------------------------------
// LSE + attentive pool: R14 structure, mma switched to fp16 m16n8k16.
// W2 stored half [ch][k] stride KST (conflict-free half2 loads); hidden layer
// computes per-lane channels {16s+2tig+{0,1,8,9}} and packs half2 B-fragments.
// C-fragment layout identical to tf32 version -> epilogue unchanged.
// ---------------------------------------------------------------------------
#define KST 72

__global__ __launch_bounds__(256) void lse_mma_kernel(
    const float* __restrict__ coords, const int* __restrict__ nidx,
    const __half* __restrict__ feats,
    const float* __restrict__ W1, const float* __restrict__ B1,
    const float* __restrict__ W2, const float* __restrict__ B2,
    __half* __restrict__ outF, int N)
{
    __shared__ float sW1[640];
    __shared__ float sB1[64];
    __shared__ float sB2[128];
    __shared__ __half sW2h[128 * KST];   // [ch][k], 18 KB

    int tid = threadIdx.x, lane = tid & 31, wid = tid >> 5;
    int gid = lane >> 2, tig = lane & 3;

    for (int i = tid; i < 640; i += 256) sW1[i] = W1[i];
    if (tid < 64) sB1[tid] = B1[tid];
    if (tid < 128) sB2[tid] = B2[tid];
    for (int i = tid; i < 8192; i += 256) {
        int k = i >> 7, ch = i & 127;
        sW2h[ch * KST + k] = __float2half_rn(W2[i]);
    }
    __syncthreads();

    int nbase = blockIdx.x * 64 + wid * 8;
    for (int p = 0; p < 8; p++) {
        int n = nbase + p;
        if (n >= N) break;

        int ib0 = nidx[n * KNBR + gid];
        int ib1 = nidx[n * KNBR + gid + 8];
        float ox = coords[n * 3], oy = coords[n * 3 + 1], oz = coords[n * 3 + 2];
        float ax = coords[ib0 * 3], ay = coords[ib0 * 3 + 1], az = coords[ib0 * 3 + 2];
        float bx = coords[ib1 * 3], by = coords[ib1 * 3 + 1], bz = coords[ib1 * 3 + 2];
        float arx = ox - ax, ary = oy - ay, arz = oz - az;
        float brx = ox - bx, bry = oy - by, brz = oz - bz;
        float ad = sqrtf(arx * arx + ary * ary + arz * arz);
        float bd = sqrtf(brx * brx + bry * bry + brz * brz);
        float ca[10] = {ox, oy, oz, ax, ay, az, arx, ary, arz, ad};
        float cb[10] = {ox, oy, oz, bx, by, bz, brx, bry, brz, bd};

        // hidden layer: lane computes channels {16s+2tig+{0,1,8,9}} per s-block
        uint32_t hb0[8], hb1[8];
#pragma unroll
        for (int s = 0; s < 4; s++) {
            float vA[4], vB[4];
#pragma unroll
            for (int d = 0; d < 4; d++) {
                int ch = 16 * s + 2 * tig + (d & 1) + 8 * (d >> 1);
                float h0 = sB1[ch], h1 = h0;
#pragma unroll
                for (int i = 0; i < 10; i++) {
                    float w = sW1[i * 64 + ch];
                    h0 = fmaf(ca[i], w, h0);
                    h1 = fmaf(cb[i], w, h1);
                }
                vA[d] = fmaxf(h0, 0.f);
                vB[d] = fmaxf(h1, 0.f);
            }
            hb0[2 * s]     = h2_u32(__floats2half2_rn(vA[0], vA[1]));
            hb0[2 * s + 1] = h2_u32(__floats2half2_rn(vA[2], vA[3]));
            hb1[2 * s]     = h2_u32(__floats2half2_rn(vB[0], vB[1]));
            hb1[2 * s + 1] = h2_u32(__floats2half2_rn(vB[2], vB[3]));
        }

        float c_[8][2][4];
#pragma unroll
        for (int mt = 0; mt < 8; mt++)
#pragma unroll
            for (int nt = 0; nt < 2; nt++)
#pragma unroll
                for (int q = 0; q < 4; q++) c_[mt][nt][q] = 0.f;

#pragma unroll
        for (int s = 0; s < 4; s++) {
            uint32_t b00 = hb0[2 * s], b01 = hb0[2 * s + 1];
            uint32_t b10 = hb1[2 * s], b11 = hb1[2 * s + 1];
            int kb = 16 * s + 2 * tig;
#pragma unroll
            for (int mt = 0; mt < 8; mt++) {
                int ch = 16 * mt + gid;
                uint32_t a0 = *(const uint32_t*)&sW2h[ch * KST + kb];
                uint32_t a1 = *(const uint32_t*)&sW2h[(ch + 8) * KST + kb];
                uint32_t a2 = *(const uint32_t*)&sW2h[ch * KST + kb + 8];
                uint32_t a3 = *(const uint32_t*)&sW2h[(ch + 8) * KST + kb + 8];
                MMA_F16(c_[mt][0], a0, a1, a2, a3, b00, b01);
                MMA_F16(c_[mt][1], a0, a1, a2, a3, b10, b11);
            }
        }

#pragma unroll
        for (int mt = 0; mt < 8; mt++) {
            float bb0 = sB2[16 * mt + gid], bb1 = sB2[16 * mt + gid + 8];
#pragma unroll
            for (int nt = 0; nt < 2; nt++) {
                c_[mt][nt][0] += bb0; c_[mt][nt][1] += bb0;
                c_[mt][nt][2] += bb1; c_[mt][nt][3] += bb1;
            }
        }

        const __half2* fp = (const __half2*)(feats + (size_t)n * 128);
        __half2 p0 = fp[2 * lane], p1 = fp[2 * lane + 1];
        float4 f4 = make_float4(__low2float(p0), __high2float(p0),
                                __low2float(p1), __high2float(p1));
        float ef[4] = {__expf(f4.x), __expf(f4.y), __expf(f4.z), __expf(f4.w)};
        float sf = ef[0] + ef[1] + ef[2] + ef[3];
#pragma unroll
        for (int o = 16; o > 0; o >>= 1)
            sf += __shfl_xor_sync(0xffffffffu, sf, o);

        float ov[8][2];
#pragma unroll
        for (int mt = 0; mt < 8; mt++) { ov[mt][0] = 0.f; ov[mt][1] = 0.f; }
        float Tl = 0.f;

#pragma unroll
        for (int j = 0; j < 4; j++) {
            int nt = j >> 1, q = j & 1;
            float e0[8], e1[8], s = 0.f;
#pragma unroll
            for (int mt = 0; mt < 8; mt++) {
                e0[mt] = __expf(c_[mt][nt][q]);
                e1[mt] = __expf(c_[mt][nt][q + 2]);
                s += e0[mt] + e1[mt];
            }
#pragma unroll
            for (int o = 4; o <= 16; o <<= 1)
                s += __shfl_xor_sync(0xffffffffu, s, o);
            float inv = 1.f / (s + sf);
            Tl += inv;
#pragma unroll
            for (int mt = 0; mt < 8; mt++) {
                ov[mt][0] = fmaf(e0[mt] * inv, c_[mt][nt][q], ov[mt][0]);
                ov[mt][1] = fmaf(e1[mt] * inv, c_[mt][nt][q + 2], ov[mt][1]);
            }
        }
        Tl += __shfl_xor_sync(0xffffffffu, Tl, 1);
        Tl += __shfl_xor_sync(0xffffffffu, Tl, 2);

#pragma unroll
        for (int mt = 0; mt < 8; mt++) {
#pragma unroll
            for (int cs = 0; cs < 2; cs++) {
                ov[mt][cs] += __shfl_xor_sync(0xffffffffu, ov[mt][cs], 1);
                ov[mt][cs] += __shfl_xor_sync(0xffffffffu, ov[mt][cs], 2);
            }
        }

        __half* po = outF + (size_t)n * 256;
#pragma unroll
        for (int t = 0; t < 2; t++) {
            int mt = 2 * tig + t;
            po[16 * mt + gid]     = __float2half_rn(ov[mt][0]);
            po[16 * mt + gid + 8] = __float2half_rn(ov[mt][1]);
        }
        __half2* gp = (__half2*)(po + 128 + 4 * lane);
        gp[0] = __floats2half2_rn(f4.x * ef[0] * Tl, f4.y * ef[1] * Tl);
        gp[1] = __floats2half2_rn(f4.z * ef[2] * Tl, f4.w * ef[3] * Tl);
    }
}

// ---------------------------------------------------------------------------
extern "C" void kernel_launch(void* const* d_in, const int* in_sizes, int n_in,
                              void* d_out, int out_size)
{
    const float* coords   = (const float*)d_in[0];
    const float* features = (const float*)d_in[1];
    const int*   nidx     = (const int*)d_in[2];
    const float* m1W1 = (const float*)d_in[3];  const float* m1b1 = (const float*)d_in[4];
    const float* m1W2 = (const float*)d_in[5];  const float* m1b2 = (const float*)d_in[6];
    const float* m2W1 = (const float*)d_in[7];  const float* m2b1 = (const float*)d_in[8];
    const float* m2W2 = (const float*)d_in[9];  const float* m2b2 = (const float*)d_in[10];
    const float* m3W1 = (const float*)d_in[11]; const float* m3b1 = (const float*)d_in[12];
    const float* m3W2 = (const float*)d_in[13]; const float* m3b2 = (const float*)d_in[14];
    const float* l1W1 = (const float*)d_in[15]; const float* l1b1 = (const float*)d_in[16];
    const float* l1W2 = (const float*)d_in[17]; const float* l1b2 = (const float*)d_in[18];
    const float* l2W1 = (const float*)d_in[19]; const float* l2b1 = (const float*)d_in[20];
    const float* l2W2 = (const float*)d_in[21]; const float* l2b2 = (const float*)d_in[22];
    const float* p1W1 = (const float*)d_in[23]; const float* p1b1 = (const float*)d_in[24];
    const float* p1W2 = (const float*)d_in[25]; const float* p1b2 = (const float*)d_in[26];
    const float* p2W1 = (const float*)d_in[27]; const float* p2b1 = (const float*)d_in[28];
    const float* p2W2 = (const float*)d_in[29]; const float* p2b2 = (const float*)d_in[30];
    float* out = (float*)d_out;

    int N = in_sizes[0] / 3;

    __half *hA, *hB, *hF, *hW, *hD;
    float* bufC;
    cudaGetSymbolAddress((void**)&hA, g_hA);
    cudaGetSymbolAddress((void**)&hB, g_hB);
    cudaGetSymbolAddress((void**)&bufC, g_bufC);
    cudaGetSymbolAddress((void**)&hF, g_hF);
    cudaGetSymbolAddress((void**)&hW, g_hW);
    cudaGetSymbolAddress((void**)&hD, g_hD);

    static cudaStream_t s2 = nullptr;
    static cudaEvent_t ev0 = nullptr, evW = nullptr, evF = nullptr, evM3 = nullptr;
    if (!s2) {
        cudaFuncSetAttribute(hgemm_kernel,
                             cudaFuncAttributeMaxDynamicSharedMemorySize,
                             HGEMM_SMEM);
        cudaFuncSetAttribute(mlp2_kernel,
                             cudaFuncAttributeMaxDynamicSharedMemorySize,
                             MLP2_SMEM);
        cudaStreamCreateWithFlags(&s2, cudaStreamNonBlocking);
        cudaEventCreateWithFlags(&ev0, cudaEventDisableTiming);
        cudaEventCreateWithFlags(&evW, cudaEventDisableTiming);
        cudaEventCreateWithFlags(&evF, cudaEventDisableTiming);
        cudaEventCreateWithFlags(&evM3, cudaEventDisableTiming);
    }

    // Weight layout in g_hW (halves):
    const int oM1W1 = 0;        // 128x128
    const int oM1W2 = 16384;    // 128x128
    const int oM2W1 = 32768;    // 384x256
    const int oM3W1 = 131072;   // 256x128
    const int oP1W1 = 163840;   // 256x256
    const int oP1W2 = 229376;   // 128x256
    const int oP2W1 = 262144;   // 256x256
    const int oP2W2 = 327680;   // 256x256
    const int oWCAT = 393216;   // 512x640  ([m2W2 | m3W2] per output row)

    WPackT wp;
    auto setw = [&](int i, const float* s, int Kd, int Od, int ld, int coff, int off) {
        wp.s[i] = s; wp.Kd[i] = Kd; wp.Od[i] = Od;
        wp.ld[i] = ld; wp.coff[i] = coff; wp.off[i] = off;
    };
    setw(0, m1W1, 128, 128, 128, 0, oM1W1);
    setw(1, m1W2, 128, 128, 128, 0, oM1W2);
    setw(2, m2W1, 256, 384, 256, 0, oM2W1);
    setw(3, m2W2, 384, 512, 640, 0, oWCAT);
    setw(4, m3W1, 128, 256, 128, 0, oM3W1);
    setw(5, m3W2, 256, 512, 640, 384, oWCAT);
    setw(6, p1W1, 256, 256, 256, 0, oP1W1);
    setw(7, p1W2, 256, 128, 256, 0, oP1W2);
    setw(8, p2W1, 256, 256, 256, 0, oP2W1);
    setw(9, p2W2, 256, 256, 256, 0, oP2W2);

    dim3 gblk(256), lblk(256);
    auto grid = [&](int M, int O) { return dim3((M + 127) / 128, O / 128); };
    dim3 mgrid((N + 127) / 128, 1);
    int lse_grid = (N + 63) / 64;
    int SB = HGEMM_SMEM;

    // ---- fork: weights round on s2, features round on legacy ----
    cudaEventRecord(ev0, 0);
    cudaStreamWaitEvent(s2, ev0, 0);
    round_weightsT_kernel<<<dim3(192, 10), 1024, 0, s2>>>(wp, hW);
    cudaEventRecord(evW, s2);

    round_feat_kernel<<<(N * 128 + 1023) / 1024, 1024>>>(features, hF, N * 128);
    cudaEventRecord(evF, 0);

    // ---- side stream: m3 hidden only (features -> 256 half) ----
    cudaStreamWaitEvent(s2, evF, 0);
    hgemm_kernel<<<grid(N, 256), gblk, SB, s2>>>(
        hF, nullptr, hW + oM3W1, m3b1, nullptr, nullptr, hD, N, 128, 0, 256, 9);
    cudaEventRecord(evM3, s2);

    // ---- main chain (legacy stream), waits for weights ----
    cudaStreamWaitEvent(0, evW, 0);
    // m1 fused: 128 -> relu 128 -> 128 (half)
    mlp2_kernel<<<mgrid, gblk, MLP2_SMEM>>>(
        hF, hW + oM1W1, m1b1, hW + oM1W2, m1b2, hB, N, 128, 128, 128);
    // lse1 -> (N,256) half
    lse_mma_kernel<<<lse_grid, lblk>>>(coords, nidx, hB, l1W1, l1b1, l1W2, l1b2, hA, N);
    // p1 fused: 256 -> relu 256 -> 128 (half)
    mlp2_kernel<<<mgrid, gblk, MLP2_SMEM>>>(
        hA, hW + oP1W1, p1b1, hW + oP1W2, p1b2, hB, N, 256, 256, 128);
    // lse2 -> (N,256) half
    lse_mma_kernel<<<lse_grid, lblk>>>(coords, nidx, hB, l2W1, l2b1, l2W2, l2b2, hA, N);
    // p2 fused: 256 -> relu 256 -> 256 (half)
    mlp2_kernel<<<mgrid, gblk, MLP2_SMEM>>>(
        hA, hW + oP2W1, p2b1, hW + oP2W2, p2b2, hB, N, 256, 256, 256);
    // m2 hidden: 256 -> 384 (relu, half)
    hgemm_kernel<<<grid(N, 384), gblk, SB>>>(
        hB, nullptr, hW + oM2W1, m2b1, nullptr, nullptr, hA, N, 256, 0, 384, 9);
    // FUSED final: leaky( [m2_hidden | m3_hidden] @ [m2W2; m3W2] + b2 + b3 )
    cudaStreamWaitEvent(0, evM3, 0);
    hgemm_kernel<<<grid(N, 512), gblk, SB>>>(
        hA, hD, hW + oWCAT, m2b2, m3b2, nullptr, out, N, 384, 256, 512, 2);
}